// round 3
// baseline (speedup 1.0000x reference)
#include <cuda_runtime.h>

#define IN_PN  20000
#define OUT_PN 5000
#define MNB    9
#define CIN    32
#define COUT   64
#define ST     64                         /* Ins row stride (floats) */
#define WST    128                        /* Wdup row stride (floats): 64 o duplicated */

#define PT_STRIDE (2*CIN*WST + 2*CIN*ST)  /* 12288 floats per point */
#define PM_OFF    (2*PT_STRIDE)           /* 24576 */
#define SMEM_FLOATS (PM_OFF + 64)

typedef unsigned long long u64;
typedef unsigned int u32;

__device__ __forceinline__ void fma2(u64& d, u64 a, u64 b) {
    asm("fma.rn.f32x2 %0, %1, %2, %0;" : "+l"(d) : "l"(a), "l"(b));
}
__device__ __forceinline__ void lds128(u64& x, u64& y, u32 addr) {
    asm volatile("ld.shared.v2.b64 {%0,%1}, [%2];" : "=l"(x), "=l"(y) : "r"(addr));
}
__device__ __forceinline__ void sts64(u32 addr, u64 v) {
    asm volatile("st.shared.b64 [%0], %1;" :: "r"(addr), "l"(v));
}
__device__ __forceinline__ void sts32(u32 addr, float v) {
    asm volatile("st.shared.f32 [%0], %1;" :: "r"(addr), "f"(v));
}
__device__ __forceinline__ u64 pack2(float lo, float hi) {
    u64 r; asm("mov.b64 %0, {%1,%2};" : "=l"(r) : "f"(lo), "f"(hi)); return r;
}
__device__ __forceinline__ void unpack2(float& lo, float& hi, u64 v) {
    asm("mov.b64 {%0,%1}, %2;" : "=f"(lo), "=f"(hi) : "l"(v));
}

// rank-32 update: acc[bp][o] += a2[bp] * wdup[o], thread tile 8b x 4o
__device__ __forceinline__ void gemm32(u32 wbase, u32 ibase, int og, int bg, u64 acc[16])
{
    #pragma unroll 8
    for (int k = 0; k < CIN; k++) {
        u64 a0, a1, a2, a3, w0, w1, w2, w3;
        u32 ia = ibase + (u32)(k * ST + bg) * 4u;
        u32 wa = wbase + (u32)(k * WST) * 4u + (u32)og * 8u;
        lds128(a0, a1, ia);
        lds128(a2, a3, ia + 16);
        lds128(w0, w1, wa);
        lds128(w2, w3, wa + 16);
        fma2(acc[ 0], a0, w0); fma2(acc[ 1], a0, w1);
        fma2(acc[ 2], a0, w2); fma2(acc[ 3], a0, w3);
        fma2(acc[ 4], a1, w0); fma2(acc[ 5], a1, w1);
        fma2(acc[ 6], a1, w2); fma2(acc[ 7], a1, w3);
        fma2(acc[ 8], a2, w0); fma2(acc[ 9], a2, w1);
        fma2(acc[10], a2, w2); fma2(acc[11], a2, w3);
        fma2(acc[12], a3, w0); fma2(acc[13], a3, w1);
        fma2(acc[14], a3, w2); fma2(acc[15], a3, w3);
    }
}

// ---- staging: 128 threads per point ----
__device__ __forceinline__ void ldgW(const float* __restrict__ src, int t, float4 wv[4])
{
    const float4* s = (const float4*)(src + (size_t)(t >> 1) * CIN + (t & 1) * 16);
    #pragma unroll
    for (int j = 0; j < 4; j++) wv[j] = s[j];
}
__device__ __forceinline__ void ldgI(const float* __restrict__ in_pc, int nv, int t, float4 iv[4])
{
    if (nv != IN_PN) {
        const float4* s = (const float4*)(in_pc + (size_t)(t >> 1) * ((size_t)IN_PN * CIN)
                                          + (size_t)nv * CIN + (t & 1) * 16);
        #pragma unroll
        for (int j = 0; j < 4; j++) iv[j] = s[j];
    } else {
        #pragma unroll
        for (int j = 0; j < 4; j++) iv[j] = make_float4(0.f, 0.f, 0.f, 0.f);
    }
}
template<bool SCALE>
__device__ __forceinline__ void stsW(u32 wbuf, int t, const float4 wv[4], float sc)
{
    int o2 = (t >> 1) * 2;
    int ch = (t & 1) * 16;
    #pragma unroll
    for (int j = 0; j < 4; j++) {
        const float* v = &wv[j].x;
        #pragma unroll
        for (int e = 0; e < 4; e++) {
            float x = SCALE ? v[e] * sc : v[e];
            sts64(wbuf + (u32)((ch + 4 * j + e) * WST + o2) * 4u, pack2(x, x));
        }
    }
}
__device__ __forceinline__ void stsI(u32 ibuf, int t, const float4 iv[4])
{
    int b  = t >> 1;
    int ch = (t & 1) * 16;
    #pragma unroll
    for (int j = 0; j < 4; j++) {
        const float* v = &iv[j].x;
        #pragma unroll
        for (int e = 0; e < 4; e++)
            sts32(ibuf + (u32)((ch + 4 * j + e) * ST + b) * 4u, v[e]);
    }
}

__global__ __launch_bounds__(256, 2)
void pconv_kernel(const float* __restrict__ in_pc,
                  const int*   __restrict__ nid_g,
                  const float* __restrict__ wts,
                  const float* __restrict__ bias,
                  const float* __restrict__ pnb,
                  const float* __restrict__ wres,
                  float* __restrict__ out)
{
    extern __shared__ float sm[];
    const u32 smb = (u32)__cvta_generic_to_shared(sm);

    const int tid = threadIdx.x;
    const int t   = tid & 127;
    const int pt  = tid >> 7;
    const int p   = blockIdx.x * 2 + pt;

    float* pm   = sm + PM_OFF + pt * 16;
    int*   nids = (int*)(sm + PM_OFF + 32) + pt * 16;

    if (t < MNB) {
        int nv = nid_g[p * MNB + t];
        nids[t] = nv;
        pm[t] = (nv != IN_PN) ? fabsf(pnb[p * MNB + t]) : 0.0f;
    }
    __syncthreads();
    if (t == 0) {
        float s = 1e-8f;
        #pragma unroll
        for (int m = 0; m < MNB; m++) s += pm[m];
        float inv = 1.0f / s;
        #pragma unroll
        for (int m = 0; m < MNB; m++) pm[m] *= inv;
    }

    const float* wp = wts + (size_t)p * (MNB * CIN * COUT);
    const u32 wbase = smb + (u32)(pt * PT_STRIDE) * 4u;            // Wdup bufs
    const u32 ibase = wbase + (u32)(2 * CIN * WST) * 4u;           // Ins bufs
    const u32 WBUF = (u32)(CIN * WST) * 4u;
    const u32 IBUF = (u32)(CIN * ST) * 4u;

    float4 wv[4], iv[4];

    // prologue: stage slice 0 into buffer 0
    ldgW(wp, t, wv);
    ldgI(in_pc, nids[0], t, iv);
    stsW<false>(wbase, t, wv, 1.0f);
    stsI(ibase, t, iv);
    __syncthreads();

    const int og = (t & 15) * 4;
    const int bg = (t >> 4) * 8;

    u64 acc[16];
    #pragma unroll
    for (int i = 0; i < 16; i++) acc[i] = 0ull;
    u64 rsv[8];
    #pragma unroll
    for (int i = 0; i < 8; i++) rsv[i] = 0ull;

    const int rc = t >> 2;          // residual: this thread owns c = rc
    const int rb = (t & 3) * 16;    // and b range [rb, rb+16)

    #pragma unroll 1
    for (int m = 0; m < MNB; m++) {
        const u32 wcur = wbase + (u32)(m & 1) * WBUF;
        const u32 icur = ibase + (u32)(m & 1) * IBUF;

        if (m < MNB - 1) {
            ldgW(wp + (size_t)(m + 1) * (CIN * COUT), t, wv);
            ldgI(in_pc, nids[m + 1], t, iv);
        }

        gemm32(wcur, icur, og, bg, acc);

        // residual pre-reduction rs[c][b] += pm[m] * I[c][b]
        {
            u64 pm2 = pack2(pm[m], pm[m]);
            u32 ra = icur + (u32)(rc * ST + rb) * 4u;
            u64 x0, x1, x2, x3, x4, x5, x6, x7;
            lds128(x0, x1, ra);      lds128(x2, x3, ra + 16);
            lds128(x4, x5, ra + 32); lds128(x6, x7, ra + 48);
            fma2(rsv[0], pm2, x0); fma2(rsv[1], pm2, x1);
            fma2(rsv[2], pm2, x2); fma2(rsv[3], pm2, x3);
            fma2(rsv[4], pm2, x4); fma2(rsv[5], pm2, x5);
            fma2(rsv[6], pm2, x6); fma2(rsv[7], pm2, x7);
        }

        if (m < MNB - 1) {
            stsW<false>(wbase + (u32)(~m & 1) * WBUF, t, wv, 1.0f);
            stsI(ibase + (u32)(~m & 1) * IBUF, t, iv);
        }
        __syncthreads();
    }

    const float C = 0.70710678118654752f;   // sqrt(0.5): both RR weights

    // stage residual operands: rs -> Ins buf0, C*weight_res (dup) -> Wdup buf0
    {
        u32 ra = ibase + (u32)(rc * ST + rb) * 4u;
        #pragma unroll
        for (int i = 0; i < 8; i++) sts64(ra + i * 8, rsv[i]);
    }
    ldgW(wres, t, wv);
    stsW<true>(wbase, t, wv, C);

    // meanwhile: acc <- C * elu(acc + bias)   (overlaps staging latency)
    {
        float4 bv = *(const float4*)(bias + (size_t)p * COUT + og);
        const float bb[4] = { bv.x, bv.y, bv.z, bv.w };
        #pragma unroll
        for (int i = 0; i < 4; i++) {
            #pragma unroll
            for (int j = 0; j < 4; j++) {
                float lo, hi;
                unpack2(lo, hi, acc[i * 4 + j]);
                lo += bb[j]; hi += bb[j];
                lo = (lo > 0.0f) ? lo : expm1f(lo);
                hi = (hi > 0.0f) ? hi : expm1f(hi);
                acc[i * 4 + j] = pack2(C * lo, C * hi);
            }
        }
    }
    __syncthreads();

    // residual GEMM (K=32) accumulates straight into acc (wres pre-scaled by C)
    gemm32(wbase, ibase, og, bg, acc);

    // store: out[b][p][o]
    #pragma unroll
    for (int i = 0; i < 4; i++) {
        float lo0, hi0, lo1, hi1, lo2, hi2, lo3, hi3;
        unpack2(lo0, hi0, acc[i * 4 + 0]);
        unpack2(lo1, hi1, acc[i * 4 + 1]);
        unpack2(lo2, hi2, acc[i * 4 + 2]);
        unpack2(lo3, hi3, acc[i * 4 + 3]);
        size_t b = (size_t)(bg + 2 * i);
        float4 v0 = { lo0, lo1, lo2, lo3 };
        float4 v1 = { hi0, hi1, hi2, hi3 };
        *(float4*)(out + (b * OUT_PN + p) * COUT + og)       = v0;
        *(float4*)(out + ((b + 1) * OUT_PN + p) * COUT + og) = v1;
    }
}

extern "C" void kernel_launch(void* const* d_in, const int* in_sizes, int n_in,
                              void* d_out, int out_size)
{
    const float* in_pc = (const float*)d_in[0];
    const int*   nid   = (const int*)  d_in[1];
    const float* wts   = (const float*)d_in[2];
    const float* bias  = (const float*)d_in[3];
    const float* pnb   = (const float*)d_in[4];
    const float* wres  = (const float*)d_in[5];
    float* out = (float*)d_out;

    const int smem_bytes = SMEM_FLOATS * sizeof(float);   // ~96.3 KB
    cudaFuncSetAttribute(pconv_kernel,
                         cudaFuncAttributeMaxDynamicSharedMemorySize, smem_bytes);

    pconv_kernel<<<OUT_PN / 2, 256, smem_bytes>>>(in_pc, nid, wts, bias, pnb, wres, out);
}

// round 5
// speedup vs baseline: 2.8039x; 2.8039x over previous
#include <cuda_runtime.h>

typedef unsigned int u32;

#define IN_PN  20000
#define OUT_PN 5000
#define MNB    9
#define CIN    32
#define COUT   64
#define SLOT   36                /* smem row stride in floats (conflict-free) */
#define TILEF  (64 * SLOT)       /* floats per 64x32 tile buffer */

__device__ __forceinline__ u32 tf32c(float x) {
    u32 r; asm("cvt.rna.tf32.f32 %0, %1;" : "=r"(r) : "f"(x)); return r;
}

__device__ __forceinline__ void mma8(float d[4], u32 a0, u32 a1, u32 a2, u32 a3,
                                     u32 b0, u32 b1) {
    asm("mma.sync.aligned.m16n8k8.row.col.f32.tf32.tf32.f32 "
        "{%0,%1,%2,%3}, {%4,%5,%6,%7}, {%8,%9}, {%0,%1,%2,%3};"
        : "+f"(d[0]), "+f"(d[1]), "+f"(d[2]), "+f"(d[3])
        : "r"(a0), "r"(a1), "r"(a2), "r"(a3), "r"(b0), "r"(b1));
}

// one 64b x 64o x 32k slice for this warp's 16b x 32o tile
__device__ __forceinline__ void slice_mma(const float* __restrict__ A,
                                          const float* __restrict__ W,
                                          int bg, int og, int g, int tig,
                                          float acc[4][4])
{
    #pragma unroll
    for (int kk = 0; kk < CIN; kk += 8) {
        u32 a0 = __float_as_uint(A[(bg + g)     * SLOT + kk + tig]);
        u32 a1 = __float_as_uint(A[(bg + g + 8) * SLOT + kk + tig]);
        u32 a2 = __float_as_uint(A[(bg + g)     * SLOT + kk + tig + 4]);
        u32 a3 = __float_as_uint(A[(bg + g + 8) * SLOT + kk + tig + 4]);
        #pragma unroll
        for (int j = 0; j < 4; j++) {
            u32 b0 = __float_as_uint(W[(og + 8 * j + g) * SLOT + kk + tig]);
            u32 b1 = __float_as_uint(W[(og + 8 * j + g) * SLOT + kk + tig + 4]);
            mma8(acc[j], a0, a1, a2, a3, b0, b1);
        }
    }
}

__device__ __forceinline__ void ldg8(float v[8], const float* __restrict__ src, bool valid) {
    if (valid) {
        float4 a = ((const float4*)src)[0];
        float4 b = ((const float4*)src)[1];
        v[0] = a.x; v[1] = a.y; v[2] = a.z; v[3] = a.w;
        v[4] = b.x; v[5] = b.y; v[6] = b.z; v[7] = b.w;
    } else {
        #pragma unroll
        for (int i = 0; i < 8; i++) v[i] = 0.0f;
    }
}

// cvt to tf32 bits + two 16B shared stores; dst 16B-aligned by construction
__device__ __forceinline__ void sts8(float* dst, const float v[8], float sc) {
    uint4 x0, x1;
    x0.x = tf32c(v[0] * sc); x0.y = tf32c(v[1] * sc);
    x0.z = tf32c(v[2] * sc); x0.w = tf32c(v[3] * sc);
    x1.x = tf32c(v[4] * sc); x1.y = tf32c(v[5] * sc);
    x1.z = tf32c(v[6] * sc); x1.w = tf32c(v[7] * sc);
    ((uint4*)dst)[0] = x0;
    ((uint4*)dst)[1] = x1;
}

__global__ __launch_bounds__(256, 2)
void pconv_mma(const float* __restrict__ in_pc,
               const int*   __restrict__ nid_g,
               const float* __restrict__ wts,
               const float* __restrict__ bias,
               const float* __restrict__ pnb,
               const float* __restrict__ wres,
               float* __restrict__ out)
{
    __shared__ float sm[4 * TILEF + 32];
    float* A0 = sm;
    float* W0 = sm + TILEF;
    float* A1 = sm + 2 * TILEF;     // also residual rs tile
    float* W1 = sm + 3 * TILEF;     // also sqrt(RR)*wres tile
    float* pm_s  = sm + 4 * TILEF;
    int*   nid_s = (int*)(sm + 4 * TILEF + 16);

    const int tid  = threadIdx.x;
    const int lane = tid & 31;
    const int wid  = tid >> 5;
    const int p    = blockIdx.x;

    const int bg  = (wid >> 1) * 16;
    const int og  = (wid & 1) * 32;
    const int g   = lane >> 2;
    const int tig = lane & 3;

    const int srow = tid >> 2;          // staging row 0..63
    const int scol = (tid & 3) * 8;     // staging col group

    if (tid < MNB) {
        int nv = nid_g[p * MNB + tid];
        nid_s[tid] = nv;
        pm_s[tid] = (nv != IN_PN) ? fabsf(pnb[p * MNB + tid]) : 0.0f;
    }
    __syncthreads();
    if (tid == 0) {
        float s = 1e-8f;
        #pragma unroll
        for (int m = 0; m < MNB; m++) s += pm_s[m];
        float inv = 1.0f / s;
        #pragma unroll
        for (int m = 0; m < MNB; m++) pm_s[m] *= inv;
    }
    __syncthreads();

    const float* wp = wts + (size_t)p * (MNB * CIN * COUT);
    const size_t in_bstride = (size_t)IN_PN * CIN;

    float rs[8];
    #pragma unroll
    for (int i = 0; i < 8; i++) rs[i] = 0.0f;
    float va[8], vw[8];

    // ---- prologue: stage slice 0 ----
    {
        int nv = nid_s[0];
        ldg8(va, in_pc + (size_t)srow * in_bstride + (size_t)nv * CIN + scol, nv != IN_PN);
        ldg8(vw, wp + (size_t)srow * CIN + scol, true);
        float pmv = pm_s[0];
        #pragma unroll
        for (int i = 0; i < 8; i++) rs[i] = fmaf(pmv, va[i], rs[i]);
        sts8(A0 + srow * SLOT + scol, va, 1.0f);
        sts8(W0 + srow * SLOT + scol, vw, 1.0f);
    }
    __syncthreads();

    float acc[4][4];
    #pragma unroll
    for (int j = 0; j < 4; j++)
        #pragma unroll
        for (int e = 0; e < 4; e++) acc[j][e] = 0.0f;

    #pragma unroll 1
    for (int m = 0; m < MNB; m++) {
        const float* Ac = (m & 1) ? A1 : A0;
        const float* Wc = (m & 1) ? W1 : W0;
        float* An = (m & 1) ? A0 : A1;
        float* Wn = (m & 1) ? W0 : W1;

        if (m < MNB - 1) {
            int nv = nid_s[m + 1];
            ldg8(va, in_pc + (size_t)srow * in_bstride + (size_t)nv * CIN + scol, nv != IN_PN);
            ldg8(vw, wp + (size_t)(m + 1) * (CIN * COUT) + (size_t)srow * CIN + scol, true);
        } else {
            ldg8(vw, wres + (size_t)srow * CIN + scol, true);   // prefetch wres
        }

        slice_mma(Ac, Wc, bg, og, g, tig, acc);

        if (m < MNB - 1) {
            float pmv = pm_s[m + 1];
            #pragma unroll
            for (int i = 0; i < 8; i++) rs[i] = fmaf(pmv, va[i], rs[i]);
            sts8(An + srow * SLOT + scol, va, 1.0f);
            sts8(Wn + srow * SLOT + scol, vw, 1.0f);
            __syncthreads();
        }
    }

    // ---- residual slice: rs (A) x sqrt(RR)*wres (B); buf1 free since m=7 ----
    const float C = 0.70710678118654752f;   // sqrt(0.5)
    sts8(A1 + srow * SLOT + scol, rs, 1.0f);
    sts8(W1 + srow * SLOT + scol, vw, C);
    __syncthreads();

    float racc[4][4];
    #pragma unroll
    for (int j = 0; j < 4; j++)
        #pragma unroll
        for (int e = 0; e < 4; e++) racc[j][e] = 0.0f;
    slice_mma(A1, W1, bg, og, g, tig, racc);

    // ---- epilogue: out = sqrt(1-RR)*elu(conv+bias) + res ----
    const float* brow = bias + (size_t)p * COUT;
    #pragma unroll
    for (int j = 0; j < 4; j++) {
        const int o0 = og + 8 * j + 2 * tig;
        float2 bb = *(const float2*)(brow + o0);

        float x0 = acc[j][0] + bb.x;
        float x1 = acc[j][1] + bb.y;
        float x2 = acc[j][2] + bb.x;
        float x3 = acc[j][3] + bb.y;
        x0 = (x0 > 0.0f) ? x0 : expm1f(x0);
        x1 = (x1 > 0.0f) ? x1 : expm1f(x1);
        x2 = (x2 > 0.0f) ? x2 : expm1f(x2);
        x3 = (x3 > 0.0f) ? x3 : expm1f(x3);

        float2 r0 = { C * x0 + racc[j][0], C * x1 + racc[j][1] };
        float2 r1 = { C * x2 + racc[j][2], C * x3 + racc[j][3] };

        *(float2*)(out + ((size_t)(bg + g)     * OUT_PN + p) * COUT + o0) = r0;
        *(float2*)(out + ((size_t)(bg + g + 8) * OUT_PN + p) * COUT + o0) = r1;
    }
}

extern "C" void kernel_launch(void* const* d_in, const int* in_sizes, int n_in,
                              void* d_out, int out_size)
{
    const float* in_pc = (const float*)d_in[0];
    const int*   nid   = (const int*)  d_in[1];
    const float* wts   = (const float*)d_in[2];
    const float* bias  = (const float*)d_in[3];
    const float* pnb   = (const float*)d_in[4];
    const float* wres  = (const float*)d_in[5];
    float* out = (float*)d_out;

    pconv_mma<<<OUT_PN, 256>>>(in_pc, nid, wts, bias, pnb, wres, out);
}

// round 6
// speedup vs baseline: 3.6407x; 1.2985x over previous
#include <cuda_runtime.h>

typedef unsigned int u32;

#define IN_PN  20000
#define OUT_PN 5000
#define MNB    9
#define CIN    32
#define COUT   64
#define SLOT   36                /* padded row stride in floats (conflict-free) */
#define TILEF  (64 * SLOT)       /* floats per 64x32 tile buffer */

__device__ __forceinline__ u32 tf32c(float x) {
    u32 r; asm("cvt.rna.tf32.f32 %0, %1;" : "=r"(r) : "f"(x)); return r;
}

__device__ __forceinline__ void mma8(float d[4], u32 a0, u32 a1, u32 a2, u32 a3,
                                     u32 b0, u32 b1) {
    asm("mma.sync.aligned.m16n8k8.row.col.f32.tf32.tf32.f32 "
        "{%0,%1,%2,%3}, {%4,%5,%6,%7}, {%8,%9}, {%0,%1,%2,%3};"
        : "+f"(d[0]), "+f"(d[1]), "+f"(d[2]), "+f"(d[3])
        : "r"(a0), "r"(a1), "r"(a2), "r"(a3), "r"(b0), "r"(b1));
}

__device__ __forceinline__ void cpasync16(u32 dst, const float* src) {
    asm volatile("cp.async.cg.shared.global [%0], [%1], 16;" :: "r"(dst), "l"(src));
}
__device__ __forceinline__ void cpcommit() {
    asm volatile("cp.async.commit_group;" ::: "memory");
}
__device__ __forceinline__ void cpwait0() {
    asm volatile("cp.async.wait_group 0;" ::: "memory");
}

// one 64x64x32 slice: this warp's 32b x 32o tile. A pre-cvt'd tf32 bits,
// W raw fp32 (cvt at read; idempotent on already-tf32 values).
__device__ __forceinline__ void slice_mma(const float* __restrict__ A,
                                          const float* __restrict__ W,
                                          int bg, int og, int g, int tig,
                                          float acc[2][4][4])
{
    #pragma unroll
    for (int kk = 0; kk < CIN; kk += 8) {
        u32 a[2][4];
        #pragma unroll
        for (int bb = 0; bb < 2; bb++) {
            const int r0 = bg + 16 * bb + g;
            a[bb][0] = __float_as_uint(A[r0       * SLOT + kk + tig]);
            a[bb][1] = __float_as_uint(A[(r0 + 8) * SLOT + kk + tig]);
            a[bb][2] = __float_as_uint(A[r0       * SLOT + kk + tig + 4]);
            a[bb][3] = __float_as_uint(A[(r0 + 8) * SLOT + kk + tig + 4]);
        }
        #pragma unroll
        for (int j = 0; j < 4; j++) {
            const int orow = og + 8 * j + g;
            u32 b0 = tf32c(W[orow * SLOT + kk + tig]);
            u32 b1 = tf32c(W[orow * SLOT + kk + tig + 4]);
            mma8(acc[0][j], a[0][0], a[0][1], a[0][2], a[0][3], b0, b1);
            mma8(acc[1][j], a[1][0], a[1][1], a[1][2], a[1][3], b0, b1);
        }
    }
}

__device__ __forceinline__ void ldg16(float v[16], const float* __restrict__ src, bool valid) {
    if (valid) {
        #pragma unroll
        for (int j = 0; j < 4; j++) {
            float4 a = ((const float4*)src)[j];
            v[4*j+0] = a.x; v[4*j+1] = a.y; v[4*j+2] = a.z; v[4*j+3] = a.w;
        }
    } else {
        #pragma unroll
        for (int i = 0; i < 16; i++) v[i] = 0.0f;
    }
}
// cvt to tf32 + 4x 16B shared stores (dst 16B aligned: SLOT*4=144, scol*4=64)
__device__ __forceinline__ void sts16(float* dst, const float v[16], float sc) {
    #pragma unroll
    for (int j = 0; j < 4; j++) {
        uint4 x;
        x.x = tf32c(v[4*j+0] * sc); x.y = tf32c(v[4*j+1] * sc);
        x.z = tf32c(v[4*j+2] * sc); x.w = tf32c(v[4*j+3] * sc);
        ((uint4*)dst)[j] = x;
    }
}

__global__ __launch_bounds__(128, 5)
void pconv_mma(const float* __restrict__ in_pc,
               const int*   __restrict__ nid_g,
               const float* __restrict__ wts,
               const float* __restrict__ bias,
               const float* __restrict__ pnb,
               const float* __restrict__ wres,
               float* __restrict__ out)
{
    __shared__ float sm[4 * TILEF + 32];
    float* A0 = sm;
    float* A1 = sm + TILEF;
    float* W0 = sm + 2 * TILEF;
    float* W1 = sm + 3 * TILEF;
    float* pm_s  = sm + 4 * TILEF;
    int*   nid_s = (int*)(sm + 4 * TILEF + 16);

    const int tid  = threadIdx.x;
    const int lane = tid & 31;
    const int wid  = tid >> 5;
    const int p    = blockIdx.x;

    const int bg  = (wid >> 1) * 32;
    const int og  = (wid & 1) * 32;
    const int g   = lane >> 2;
    const int tig = lane & 3;

    const int srow = tid >> 1;          // staging row 0..63
    const int scol = (tid & 1) * 16;    // 16-float half

    if (tid < MNB) {
        int nv = nid_g[p * MNB + tid];
        nid_s[tid] = nv;
        pm_s[tid] = (nv != IN_PN) ? fabsf(pnb[p * MNB + tid]) : 0.0f;
    }
    __syncthreads();
    if (tid == 0) {
        float s = 1e-8f;
        #pragma unroll
        for (int m = 0; m < MNB; m++) s += pm_s[m];
        float inv = 1.0f / s;
        #pragma unroll
        for (int m = 0; m < MNB; m++) pm_s[m] *= inv;
    }
    __syncthreads();

    const float* wp = wts + (size_t)p * (MNB * CIN * COUT);
    const size_t in_bstride = (size_t)IN_PN * CIN;
    const u32 smbase = (u32)__cvta_generic_to_shared(sm);
    const u32 wdst_off = (u32)(srow * SLOT + scol) * 4u;

    float rs[16];
    #pragma unroll
    for (int i = 0; i < 16; i++) rs[i] = 0.0f;
    float va[16];

    // ---- prologue: stage slice 0 ----
    {
        const float* wsrc = wp + (size_t)srow * CIN + scol;
        u32 wdst = smbase + (u32)(2 * TILEF) * 4u + wdst_off;   // W0
        #pragma unroll
        for (int j = 0; j < 4; j++) cpasync16(wdst + 16u * j, wsrc + 4 * j);
        cpcommit();

        int nv = nid_s[0];
        ldg16(va, in_pc + (size_t)srow * in_bstride + (size_t)nv * CIN + scol, nv != IN_PN);
        float pmv = pm_s[0];
        #pragma unroll
        for (int i = 0; i < 16; i++) rs[i] = fmaf(pmv, va[i], rs[i]);
        sts16(A0 + srow * SLOT + scol, va, 1.0f);
        cpwait0();
    }
    __syncthreads();

    float acc[2][4][4];
    #pragma unroll
    for (int b = 0; b < 2; b++)
        #pragma unroll
        for (int j = 0; j < 4; j++)
            #pragma unroll
            for (int e = 0; e < 4; e++) acc[b][j][e] = 0.0f;

    #pragma unroll 1
    for (int m = 0; m < MNB; m++) {
        const float* Ac = (m & 1) ? A1 : A0;
        const float* Wc = (m & 1) ? W1 : W0;
        float* An = (m & 1) ? A0 : A1;
        const u32 WnOff = (u32)((m & 1) ? 2 * TILEF : 3 * TILEF) * 4u;

        if (m < MNB - 1) {
            const float* wsrc = wp + (size_t)(m + 1) * (CIN * COUT) + (size_t)srow * CIN + scol;
            u32 wdst = smbase + WnOff + wdst_off;
            #pragma unroll
            for (int j = 0; j < 4; j++) cpasync16(wdst + 16u * j, wsrc + 4 * j);
            cpcommit();

            int nv = nid_s[m + 1];
            ldg16(va, in_pc + (size_t)srow * in_bstride + (size_t)nv * CIN + scol, nv != IN_PN);
        }

        slice_mma(Ac, Wc, bg, og, g, tig, acc);

        if (m < MNB - 1) {
            float pmv = pm_s[m + 1];
            #pragma unroll
            for (int i = 0; i < 16; i++) rs[i] = fmaf(pmv, va[i], rs[i]);
            sts16(An + srow * SLOT + scol, va, 1.0f);
            cpwait0();
            __syncthreads();
        }
    }

    // ---- residual slice into freed buffer 1 (last main slice used buffer 0) ----
    const float C = 0.70710678118654752f;   // sqrt(0.5)
    sts16(A1 + srow * SLOT + scol, rs, 1.0f);
    {
        float vw[16];
        ldg16(vw, wres + (size_t)srow * CIN + scol, true);
        sts16(W1 + srow * SLOT + scol, vw, C);   // pre-scaled by sqrt(RR)
    }

    // transform acc in the shadow of staging: acc <- C * elu(acc + bias)
    const float* brow = bias + (size_t)p * COUT;
    #pragma unroll
    for (int j = 0; j < 4; j++) {
        const int o0 = og + 8 * j + 2 * tig;
        float2 bb = *(const float2*)(brow + o0);
        #pragma unroll
        for (int b = 0; b < 2; b++) {
            float x0 = acc[b][j][0] + bb.x;
            float x1 = acc[b][j][1] + bb.y;
            float x2 = acc[b][j][2] + bb.x;
            float x3 = acc[b][j][3] + bb.y;
            x0 = (x0 > 0.0f) ? x0 : expm1f(x0);
            x1 = (x1 > 0.0f) ? x1 : expm1f(x1);
            x2 = (x2 > 0.0f) ? x2 : expm1f(x2);
            x3 = (x3 > 0.0f) ? x3 : expm1f(x3);
            acc[b][j][0] = C * x0; acc[b][j][1] = C * x1;
            acc[b][j][2] = C * x2; acc[b][j][3] = C * x3;
        }
    }
    __syncthreads();

    // residual MMA accumulates in place (wres pre-scaled)
    slice_mma(A1, W1, bg, og, g, tig, acc);

    // ---- store: out[b][p][o] ----
    #pragma unroll
    for (int j = 0; j < 4; j++) {
        const int o0 = og + 8 * j + 2 * tig;
        #pragma unroll
        for (int b = 0; b < 2; b++) {
            const int r0 = bg + 16 * b + g;
            float2 v0 = { acc[b][j][0], acc[b][j][1] };
            float2 v1 = { acc[b][j][2], acc[b][j][3] };
            *(float2*)(out + ((size_t)r0       * OUT_PN + p) * COUT + o0) = v0;
            *(float2*)(out + ((size_t)(r0 + 8) * OUT_PN + p) * COUT + o0) = v1;
        }
    }
}

extern "C" void kernel_launch(void* const* d_in, const int* in_sizes, int n_in,
                              void* d_out, int out_size)
{
    const float* in_pc = (const float*)d_in[0];
    const int*   nid   = (const int*)  d_in[1];
    const float* wts   = (const float*)d_in[2];
    const float* bias  = (const float*)d_in[3];
    const float* pnb   = (const float*)d_in[4];
    const float* wres  = (const float*)d_in[5];
    float* out = (float*)d_out;

    pconv_mma<<<OUT_PN, 128>>>(in_pc, nid, wts, bias, pnb, wres, out);
}